// round 4
// baseline (speedup 1.0000x reference)
#include <cuda_runtime.h>
#include <math.h>

#define NV    500000
#define ND    128
#define NEDGE 1000000

// ---------------- scratch (device globals; allocation-free launch) ----------
__device__ float  g_proj[NV];
__device__ float  g_deg[NV];           // deg, then overwritten with dinv
__device__ float4 g_m0[NV * 2];        // 8 floats per node (ping)
__device__ float4 g_m1[NV * 2];        // 8 floats per node (pong)
__device__ int2   g_edge[NEDGE];       // (Se, Ie)
__device__ int2   g_entry[2 * NEDGE];  // CSR entries: (src, w as float bits)
__device__ int    g_rs[NV];            // CSR row start
__device__ int    g_cur[NV];           // fill cursor; after fill: row end
__device__ int    g_cursor;
__device__ int    g_is64;

// ---------------- K1: fused proj = X@rv and A = X@W1, deg init --------------
// 8 lanes per row, 4 rows per warp: MLP=4 per lane, 3-round reductions.
__global__ void __launch_bounds__(256) k_proj_w1(
        const float* __restrict__ X,
        const float* __restrict__ rv,
        const float* __restrict__ W1,
        const unsigned* __restrict__ E) {
    if (blockIdx.x == 0 && threadIdx.x == 0) {
        // dtype detection (E int64 vs silently-downcast int32):
        // values < 500000 => int64 high words all zero.
        unsigned o = 0;
#pragma unroll
        for (int i = 0; i < 128; i++) o |= E[2 * i + 1];
        g_is64 = (o == 0) ? 1 : 0;
        g_cursor = 0;
    }

    __shared__ float4 sW[8 * 32];   // sW[h*32 + d4] = W1 rows 4*d4..4*d4+3, col h
    __shared__ float4 sr[32];
    int t = threadIdx.x;
    for (int i = t; i < 1024; i += 256) {
        int d = i >> 3, h = i & 7;
        ((float*)sW)[h * 128 + d] = W1[i];
    }
    if (t < 128) ((float*)sr)[t] = rv[t];
    __syncthreads();

    int lane = t & 31;
    int sub  = lane & 7;            // 0..7 : position within row
    int rloc = lane >> 3;           // 0..3 : row within warp
    int warp = (blockIdx.x * 256 + t) >> 5;
    int row  = warp * 4 + rloc;
    if (row >= NV) return;

    const float4* Xr = (const float4*)X + (size_t)row * 32;
    float p = 0.f;
    float a[8] = {0.f, 0.f, 0.f, 0.f, 0.f, 0.f, 0.f, 0.f};
#pragma unroll
    for (int i = 0; i < 4; i++) {
        int d4 = sub + i * 8;
        float4 x = __ldcs(&Xr[d4]);
        float4 r = sr[d4];
        p += x.x * r.x + x.y * r.y + x.z * r.z + x.w * r.w;
#pragma unroll
        for (int h = 0; h < 8; h++) {
            float4 w = sW[h * 32 + d4];
            a[h] += x.x * w.x + x.y * w.y + x.z * w.z + x.w * w.w;
        }
    }
#pragma unroll
    for (int o = 4; o; o >>= 1) {
        p += __shfl_down_sync(0xffffffffu, p, o);
#pragma unroll
        for (int h = 0; h < 8; h++) a[h] += __shfl_down_sync(0xffffffffu, a[h], o);
    }
    if (sub == 0) {
        g_proj[row] = p;
        g_m0[row * 2]     = make_float4(a[0], a[1], a[2], a[3]);
        g_m0[row * 2 + 1] = make_float4(a[4], a[5], a[6], a[7]);
        g_deg[row] = 1.0f;   // identity contribution
    }
}

// ---------------- K2: per-hyperedge argmax/argmin + degree atomics ----------
__global__ void __launch_bounds__(256) k_edges(const void* __restrict__ E) {
    int e = blockIdx.x * blockDim.x + threadIdx.x;
    if (e >= NEDGE) return;
    int idx[8];
    if (g_is64) {
        const longlong4* p = (const longlong4*)E;
        longlong4 u = p[e * 2], v = p[e * 2 + 1];
        idx[0] = (int)u.x; idx[1] = (int)u.y; idx[2] = (int)u.z; idx[3] = (int)u.w;
        idx[4] = (int)v.x; idx[5] = (int)v.y; idx[6] = (int)v.z; idx[7] = (int)v.w;
    } else {
        const int4* p = (const int4*)E;
        int4 u = p[e * 2], v = p[e * 2 + 1];
        idx[0] = u.x; idx[1] = u.y; idx[2] = u.z; idx[3] = u.w;
        idx[4] = v.x; idx[5] = v.y; idx[6] = v.z; idx[7] = v.w;
    }
    float pv[8];
#pragma unroll
    for (int k = 0; k < 8; k++) pv[k] = __ldg(&g_proj[idx[k]]);
    // strict compares -> first occurrence, matching jnp.argmax/argmin
    int S = idx[0], I = idx[0];
    float mx = pv[0], mn = pv[0];
#pragma unroll
    for (int k = 1; k < 8; k++) {
        if (pv[k] > mx) { mx = pv[k]; S = idx[k]; }
        if (pv[k] < mn) { mn = pv[k]; I = idx[k]; }
    }
    g_edge[e] = make_int2(S, I);
    atomicAdd(&g_deg[S], 0.125f);
    atomicAdd(&g_deg[I], 0.125f);
}

// ---------------- K3: dinv = rsqrt(deg); CSR row allocation -----------------
__global__ void __launch_bounds__(256) k_norm() {
    int v = blockIdx.x * blockDim.x + threadIdx.x;
    if (v >= NV) return;
    float dg = g_deg[v];
    g_deg[v] = rsqrtf(dg);                       // now holds dinv
    int cnt = __float2int_rn((dg - 1.0f) * 8.0f);  // exact: deg steps are 1/8
    int rs = cnt ? atomicAdd(&g_cursor, cnt) : 0;
    g_rs[v]  = rs;
    g_cur[v] = rs;
}

// ---------------- K4: fill CSR entries (src, w) per endpoint ----------------
__global__ void __launch_bounds__(256) k_fill() {
    int e = blockIdx.x * blockDim.x + threadIdx.x;
    if (e >= NEDGE) return;
    int2 si = g_edge[e];
    float w = 0.125f * __ldg(&g_deg[si.x]) * __ldg(&g_deg[si.y]);
    int wb = __float_as_int(w);
    int p1 = atomicAdd(&g_cur[si.x], 1);
    g_entry[p1] = make_int2(si.y, wb);
    int p2 = atomicAdd(&g_cur[si.y], 1);
    g_entry[p2] = make_int2(si.x, wb);
}

// ---------------- pull: s = dinv^2*M[v] + sum w*M[src]  (no atomics) --------
__device__ __forceinline__ void pull_row(int v, const float4* __restrict__ M,
                                         float* __restrict__ s) {
    float d  = g_deg[v];
    float dd = d * d;
    int rs  = g_rs[v];
    int re  = g_cur[v];
    float4 a = M[2 * v], b = M[2 * v + 1];
    s[0] = dd * a.x; s[1] = dd * a.y; s[2] = dd * a.z; s[3] = dd * a.w;
    s[4] = dd * b.x; s[5] = dd * b.y; s[6] = dd * b.z; s[7] = dd * b.w;
    int i = rs;
    for (; i + 2 <= re; i += 2) {
        int2 e0 = __ldg(&g_entry[i]);
        int2 e1 = __ldg(&g_entry[i + 1]);
        float w0 = __int_as_float(e0.y), w1 = __int_as_float(e1.y);
        float4 a0 = __ldg(&M[2 * e0.x]), b0 = __ldg(&M[2 * e0.x + 1]);
        float4 a1 = __ldg(&M[2 * e1.x]), b1 = __ldg(&M[2 * e1.x + 1]);
        s[0] += w0 * a0.x + w1 * a1.x; s[1] += w0 * a0.y + w1 * a1.y;
        s[2] += w0 * a0.z + w1 * a1.z; s[3] += w0 * a0.w + w1 * a1.w;
        s[4] += w0 * b0.x + w1 * b1.x; s[5] += w0 * b0.y + w1 * b1.y;
        s[6] += w0 * b0.z + w1 * b1.z; s[7] += w0 * b0.w + w1 * b1.w;
    }
    if (i < re) {
        int2 e0 = __ldg(&g_entry[i]);
        float w0 = __int_as_float(e0.y);
        float4 a0 = __ldg(&M[2 * e0.x]), b0 = __ldg(&M[2 * e0.x + 1]);
        s[0] += w0 * a0.x; s[1] += w0 * a0.y; s[2] += w0 * a0.z; s[3] += w0 * a0.w;
        s[4] += w0 * b0.x; s[5] += w0 * b0.y; s[6] += w0 * b0.z; s[7] += w0 * b0.w;
    }
}

// ---- pull layer 1: m1 = relu(spmm(m0)+b1) @ W2 -----------------------------
__global__ void __launch_bounds__(256) k_pull1(const float* __restrict__ W2,
                                               const float* __restrict__ b1) {
    __shared__ float sW[64], sb[8];
    int t = threadIdx.x;
    if (t < 64) sW[t] = W2[t];
    if (t < 8)  sb[t] = b1[t];
    __syncthreads();
    int v = blockIdx.x * 256 + t;
    if (v >= NV) return;
    float s[8];
    pull_row(v, g_m0, s);
    float h[8];
#pragma unroll
    for (int k = 0; k < 8; k++) h[k] = fmaxf(s[k] + sb[k], 0.f);
    float m[8];
#pragma unroll
    for (int j = 0; j < 8; j++) {
        float acc = 0.f;
#pragma unroll
        for (int k = 0; k < 8; k++) acc += h[k] * sW[k * 8 + j];
        m[j] = acc;
    }
    g_m1[2 * v]     = make_float4(m[0], m[1], m[2], m[3]);
    g_m1[2 * v + 1] = make_float4(m[4], m[5], m[6], m[7]);
}

// ---- pull layer 2: m0 = relu(spmm(m1)+b2)  (W3 deferred via linearity) -----
__global__ void __launch_bounds__(256) k_pull2(const float* __restrict__ b2) {
    __shared__ float sb[8];
    int t = threadIdx.x;
    if (t < 8) sb[t] = b2[t];
    __syncthreads();
    int v = blockIdx.x * 256 + t;
    if (v >= NV) return;
    float s[8];
    pull_row(v, g_m1, s);
    float4 h0 = make_float4(fmaxf(s[0] + sb[0], 0.f), fmaxf(s[1] + sb[1], 0.f),
                            fmaxf(s[2] + sb[2], 0.f), fmaxf(s[3] + sb[3], 0.f));
    float4 h1 = make_float4(fmaxf(s[4] + sb[4], 0.f), fmaxf(s[5] + sb[5], 0.f),
                            fmaxf(s[6] + sb[6], 0.f), fmaxf(s[7] + sb[7], 0.f));
    g_m0[2 * v]     = h0;
    g_m0[2 * v + 1] = h1;
}

// ---- pull layer 3 + head: out = sigmoid(relu(spmm(m0)@W3+b3)@fc+fcb) -------
__global__ void __launch_bounds__(256) k_pull3(
        const float* __restrict__ W3, const float* __restrict__ b3,
        const float* __restrict__ fcw, const float* __restrict__ fcb,
        float* __restrict__ out) {
    __shared__ float sW[8 * 16], sb3[16], sfw[16], sfb;
    int t = threadIdx.x;
    if (t < 128) sW[t] = W3[t];
    if (t < 16) { sb3[t] = b3[t]; sfw[t] = fcw[t]; }
    if (t == 0) sfb = fcb[0];
    __syncthreads();
    int v = blockIdx.x * 256 + t;
    if (v >= NV) return;
    float s[8];
    pull_row(v, g_m0, s);
    float logit = sfb;
#pragma unroll
    for (int c = 0; c < 16; c++) {
        float tt = sb3[c];
#pragma unroll
        for (int h = 0; h < 8; h++) tt += s[h] * sW[h * 16 + c];
        logit += fmaxf(tt, 0.f) * sfw[c];
    }
    out[v] = 1.0f / (1.0f + expf(-logit));
}

// ---------------- launch ----------------------------------------------------
extern "C" void kernel_launch(void* const* d_in, const int* in_sizes, int n_in,
                              void* d_out, int out_size) {
    const float* X   = (const float*)d_in[0];
    const void*  E   = d_in[1];
    const float* rv  = (const float*)d_in[2];
    const float* W1  = (const float*)d_in[3];
    const float* b1  = (const float*)d_in[4];
    const float* W2  = (const float*)d_in[5];
    const float* b2  = (const float*)d_in[6];
    const float* W3  = (const float*)d_in[7];
    const float* b3  = (const float*)d_in[8];
    const float* fcw = (const float*)d_in[9];
    const float* fcb = (const float*)d_in[10];
    float* out = (float*)d_out;

    const int NB_V = (NV + 255) / 256;       // 1954
    const int NB_E = (NEDGE + 255) / 256;    // 3907
    const int NB_W = (NV * 8 + 255) / 256;   // 15625 (8 lanes per row)

    k_proj_w1<<<NB_W, 256>>>(X, rv, W1, (const unsigned*)E);
    k_edges<<<NB_E, 256>>>(E);
    k_norm<<<NB_V, 256>>>();
    k_fill<<<NB_E, 256>>>();
    k_pull1<<<NB_V, 256>>>(W2, b1);
    k_pull2<<<NB_V, 256>>>(b2);
    k_pull3<<<NB_V, 256>>>(W3, b3, fcw, fcb, out);
}

// round 5
// speedup vs baseline: 1.0034x; 1.0034x over previous
#include <cuda_runtime.h>
#include <math.h>

#define NV    500000
#define ND    128
#define NEDGE 1000000

// ---------------- scratch (device globals; allocation-free launch) ----------
__device__ float  g_proj[NV];
__device__ float  g_deg[NV];           // deg, then overwritten with dinv
__device__ float4 g_m0[NV * 2];        // 8 floats per node (ping)
__device__ float4 g_m1[NV * 2];        // 8 floats per node (pong)
__device__ int2   g_edge[NEDGE];       // (Se, Ie)
__device__ int2   g_entry[2 * NEDGE];  // CSR entries: (src, w as float bits)
__device__ int    g_rs[NV];            // CSR row start
__device__ int    g_cur[NV];           // fill cursor; after fill: row end
__device__ int    g_cursor;
__device__ int    g_is64;

// ---------------- K1: fused proj = X@rv and A = X@W1, deg init --------------
// 8 lanes per row, 4 rows per warp: MLP=4 per lane, 3-round reductions.
__global__ void __launch_bounds__(256) k_proj_w1(
        const float* __restrict__ X,
        const float* __restrict__ rv,
        const float* __restrict__ W1,
        const unsigned* __restrict__ E) {
    if (blockIdx.x == 0 && threadIdx.x == 0) {
        // dtype detection (E int64 vs silently-downcast int32):
        // values < 500000 => int64 high words all zero.
        unsigned o = 0;
#pragma unroll
        for (int i = 0; i < 128; i++) o |= E[2 * i + 1];
        g_is64 = (o == 0) ? 1 : 0;
        g_cursor = 0;
    }

    __shared__ float4 sW[8 * 32];   // sW[h*32 + d4] = W1 rows 4*d4..4*d4+3, col h
    __shared__ float4 sr[32];
    int t = threadIdx.x;
    for (int i = t; i < 1024; i += 256) {
        int d = i >> 3, h = i & 7;
        ((float*)sW)[h * 128 + d] = W1[i];
    }
    if (t < 128) ((float*)sr)[t] = rv[t];
    __syncthreads();

    int lane = t & 31;
    int sub  = lane & 7;            // 0..7 : position within row
    int rloc = lane >> 3;           // 0..3 : row within warp
    int warp = (blockIdx.x * 256 + t) >> 5;
    int row  = warp * 4 + rloc;
    if (row >= NV) return;

    const float4* Xr = (const float4*)X + (size_t)row * 32;
    float p = 0.f;
    float a[8] = {0.f, 0.f, 0.f, 0.f, 0.f, 0.f, 0.f, 0.f};
#pragma unroll
    for (int i = 0; i < 4; i++) {
        int d4 = sub + i * 8;
        float4 x = __ldcs(&Xr[d4]);
        float4 r = sr[d4];
        p += x.x * r.x + x.y * r.y + x.z * r.z + x.w * r.w;
#pragma unroll
        for (int h = 0; h < 8; h++) {
            float4 w = sW[h * 32 + d4];
            a[h] += x.x * w.x + x.y * w.y + x.z * w.z + x.w * w.w;
        }
    }
#pragma unroll
    for (int o = 4; o; o >>= 1) {
        p += __shfl_down_sync(0xffffffffu, p, o);
#pragma unroll
        for (int h = 0; h < 8; h++) a[h] += __shfl_down_sync(0xffffffffu, a[h], o);
    }
    if (sub == 0) {
        g_proj[row] = p;
        g_m0[row * 2]     = make_float4(a[0], a[1], a[2], a[3]);
        g_m0[row * 2 + 1] = make_float4(a[4], a[5], a[6], a[7]);
        g_deg[row] = 1.0f;   // identity contribution
    }
}

// ---------------- K2: per-hyperedge argmax/argmin + degree atomics ----------
__global__ void __launch_bounds__(256) k_edges(const void* __restrict__ E) {
    int e = blockIdx.x * blockDim.x + threadIdx.x;
    if (e >= NEDGE) return;
    int idx[8];
    if (g_is64) {
        const longlong4* p = (const longlong4*)E;
        longlong4 u = p[e * 2], v = p[e * 2 + 1];
        idx[0] = (int)u.x; idx[1] = (int)u.y; idx[2] = (int)u.z; idx[3] = (int)u.w;
        idx[4] = (int)v.x; idx[5] = (int)v.y; idx[6] = (int)v.z; idx[7] = (int)v.w;
    } else {
        const int4* p = (const int4*)E;
        int4 u = p[e * 2], v = p[e * 2 + 1];
        idx[0] = u.x; idx[1] = u.y; idx[2] = u.z; idx[3] = u.w;
        idx[4] = v.x; idx[5] = v.y; idx[6] = v.z; idx[7] = v.w;
    }
    float pv[8];
#pragma unroll
    for (int k = 0; k < 8; k++) pv[k] = __ldg(&g_proj[idx[k]]);
    // strict compares -> first occurrence, matching jnp.argmax/argmin
    int S = idx[0], I = idx[0];
    float mx = pv[0], mn = pv[0];
#pragma unroll
    for (int k = 1; k < 8; k++) {
        if (pv[k] > mx) { mx = pv[k]; S = idx[k]; }
        if (pv[k] < mn) { mn = pv[k]; I = idx[k]; }
    }
    g_edge[e] = make_int2(S, I);
    atomicAdd(&g_deg[S], 0.125f);
    atomicAdd(&g_deg[I], 0.125f);
}

// ---------------- K3: dinv = rsqrt(deg); CSR row allocation -----------------
__global__ void __launch_bounds__(256) k_norm() {
    int v = blockIdx.x * blockDim.x + threadIdx.x;
    if (v >= NV) return;
    float dg = g_deg[v];
    g_deg[v] = rsqrtf(dg);                       // now holds dinv
    int cnt = __float2int_rn((dg - 1.0f) * 8.0f);  // exact: deg steps are 1/8
    int rs = cnt ? atomicAdd(&g_cursor, cnt) : 0;
    g_rs[v]  = rs;
    g_cur[v] = rs;
}

// ---------------- K4: fill CSR entries (src, w) per endpoint ----------------
__global__ void __launch_bounds__(256) k_fill() {
    int e = blockIdx.x * blockDim.x + threadIdx.x;
    if (e >= NEDGE) return;
    int2 si = g_edge[e];
    float w = 0.125f * __ldg(&g_deg[si.x]) * __ldg(&g_deg[si.y]);
    int wb = __float_as_int(w);
    int p1 = atomicAdd(&g_cur[si.x], 1);
    g_entry[p1] = make_int2(si.y, wb);
    int p2 = atomicAdd(&g_cur[si.y], 1);
    g_entry[p2] = make_int2(si.x, wb);
}

// ---------------- pull: s = dinv^2*M[v] + sum w*M[src]  (no atomics) --------
__device__ __forceinline__ void pull_row(int v, const float4* __restrict__ M,
                                         float* __restrict__ s) {
    float d  = g_deg[v];
    float dd = d * d;
    int rs  = g_rs[v];
    int re  = g_cur[v];
    float4 a = M[2 * v], b = M[2 * v + 1];
    s[0] = dd * a.x; s[1] = dd * a.y; s[2] = dd * a.z; s[3] = dd * a.w;
    s[4] = dd * b.x; s[5] = dd * b.y; s[6] = dd * b.z; s[7] = dd * b.w;
    int i = rs;
    for (; i + 2 <= re; i += 2) {
        int2 e0 = __ldg(&g_entry[i]);
        int2 e1 = __ldg(&g_entry[i + 1]);
        float w0 = __int_as_float(e0.y), w1 = __int_as_float(e1.y);
        float4 a0 = __ldg(&M[2 * e0.x]), b0 = __ldg(&M[2 * e0.x + 1]);
        float4 a1 = __ldg(&M[2 * e1.x]), b1 = __ldg(&M[2 * e1.x + 1]);
        s[0] += w0 * a0.x + w1 * a1.x; s[1] += w0 * a0.y + w1 * a1.y;
        s[2] += w0 * a0.z + w1 * a1.z; s[3] += w0 * a0.w + w1 * a1.w;
        s[4] += w0 * b0.x + w1 * b1.x; s[5] += w0 * b0.y + w1 * b1.y;
        s[6] += w0 * b0.z + w1 * b1.z; s[7] += w0 * b0.w + w1 * b1.w;
    }
    if (i < re) {
        int2 e0 = __ldg(&g_entry[i]);
        float w0 = __int_as_float(e0.y);
        float4 a0 = __ldg(&M[2 * e0.x]), b0 = __ldg(&M[2 * e0.x + 1]);
        s[0] += w0 * a0.x; s[1] += w0 * a0.y; s[2] += w0 * a0.z; s[3] += w0 * a0.w;
        s[4] += w0 * b0.x; s[5] += w0 * b0.y; s[6] += w0 * b0.z; s[7] += w0 * b0.w;
    }
}

// ---- pull layer 1: m1 = relu(spmm(m0)+b1) @ W2 -----------------------------
__global__ void __launch_bounds__(256) k_pull1(const float* __restrict__ W2,
                                               const float* __restrict__ b1) {
    __shared__ float sW[64], sb[8];
    int t = threadIdx.x;
    if (t < 64) sW[t] = W2[t];
    if (t < 8)  sb[t] = b1[t];
    __syncthreads();
    int v = blockIdx.x * 256 + t;
    if (v >= NV) return;
    float s[8];
    pull_row(v, g_m0, s);
    float h[8];
#pragma unroll
    for (int k = 0; k < 8; k++) h[k] = fmaxf(s[k] + sb[k], 0.f);
    float m[8];
#pragma unroll
    for (int j = 0; j < 8; j++) {
        float acc = 0.f;
#pragma unroll
        for (int k = 0; k < 8; k++) acc += h[k] * sW[k * 8 + j];
        m[j] = acc;
    }
    g_m1[2 * v]     = make_float4(m[0], m[1], m[2], m[3]);
    g_m1[2 * v + 1] = make_float4(m[4], m[5], m[6], m[7]);
}

// ---- pull layer 2: m0 = relu(spmm(m1)+b2)  (W3 deferred via linearity) -----
__global__ void __launch_bounds__(256) k_pull2(const float* __restrict__ b2) {
    __shared__ float sb[8];
    int t = threadIdx.x;
    if (t < 8) sb[t] = b2[t];
    __syncthreads();
    int v = blockIdx.x * 256 + t;
    if (v >= NV) return;
    float s[8];
    pull_row(v, g_m1, s);
    float4 h0 = make_float4(fmaxf(s[0] + sb[0], 0.f), fmaxf(s[1] + sb[1], 0.f),
                            fmaxf(s[2] + sb[2], 0.f), fmaxf(s[3] + sb[3], 0.f));
    float4 h1 = make_float4(fmaxf(s[4] + sb[4], 0.f), fmaxf(s[5] + sb[5], 0.f),
                            fmaxf(s[6] + sb[6], 0.f), fmaxf(s[7] + sb[7], 0.f));
    g_m0[2 * v]     = h0;
    g_m0[2 * v + 1] = h1;
}

// ---- pull layer 3 + head: out = sigmoid(relu(spmm(m0)@W3+b3)@fc+fcb) -------
__global__ void __launch_bounds__(256) k_pull3(
        const float* __restrict__ W3, const float* __restrict__ b3,
        const float* __restrict__ fcw, const float* __restrict__ fcb,
        float* __restrict__ out) {
    __shared__ float sW[8 * 16], sb3[16], sfw[16], sfb;
    int t = threadIdx.x;
    if (t < 128) sW[t] = W3[t];
    if (t < 16) { sb3[t] = b3[t]; sfw[t] = fcw[t]; }
    if (t == 0) sfb = fcb[0];
    __syncthreads();
    int v = blockIdx.x * 256 + t;
    if (v >= NV) return;
    float s[8];
    pull_row(v, g_m0, s);
    float logit = sfb;
#pragma unroll
    for (int c = 0; c < 16; c++) {
        float tt = sb3[c];
#pragma unroll
        for (int h = 0; h < 8; h++) tt += s[h] * sW[h * 16 + c];
        logit += fmaxf(tt, 0.f) * sfw[c];
    }
    out[v] = 1.0f / (1.0f + expf(-logit));
}

// ---------------- launch ----------------------------------------------------
extern "C" void kernel_launch(void* const* d_in, const int* in_sizes, int n_in,
                              void* d_out, int out_size) {
    const float* X   = (const float*)d_in[0];
    const void*  E   = d_in[1];
    const float* rv  = (const float*)d_in[2];
    const float* W1  = (const float*)d_in[3];
    const float* b1  = (const float*)d_in[4];
    const float* W2  = (const float*)d_in[5];
    const float* b2  = (const float*)d_in[6];
    const float* W3  = (const float*)d_in[7];
    const float* b3  = (const float*)d_in[8];
    const float* fcw = (const float*)d_in[9];
    const float* fcb = (const float*)d_in[10];
    float* out = (float*)d_out;

    const int NB_V = (NV + 255) / 256;       // 1954
    const int NB_E = (NEDGE + 255) / 256;    // 3907
    const int NB_W = (NV * 8 + 255) / 256;   // 15625 (8 lanes per row)

    k_proj_w1<<<NB_W, 256>>>(X, rv, W1, (const unsigned*)E);
    k_edges<<<NB_E, 256>>>(E);
    k_norm<<<NB_V, 256>>>();
    k_fill<<<NB_E, 256>>>();
    k_pull1<<<NB_V, 256>>>(W2, b1);
    k_pull2<<<NB_V, 256>>>(b2);
    k_pull3<<<NB_V, 256>>>(W3, b3, fcw, fcb, out);
}